// round 6
// baseline (speedup 1.0000x reference)
#include <cuda_runtime.h>

// SPU transformer: N=8192 rows elementwise. 4 rows per thread (2x float4 per
// array, 8 front-batched LDG.128 -> MLP=8 per thread). 16 CTAs x 128 threads.
// Fast-math sigmoid: sigmoid(-x)-1 = -e^x/(1+e^x). rel_err ~2.5e-7.

__device__ __forceinline__ float2 spu_row(float l, float u,
                                          float ls_l, float ls_u,
                                          float lsh_l, float lsh_u,
                                          float lb_l, float lb_u) {
    float el = __expf(l);
    float eu = __expf(u);
    float vl_neg = __fdividef(-el, 1.0f + el);
    float vu_neg = __fdividef(-eu, 1.0f + eu);
    float vl = (l >= 0.0f) ? fmaf(l, l, -0.5f) : vl_neg;
    float vu = (u >= 0.0f) ? fmaf(u, u, -0.5f) : vu_neg;

    bool neg   = (u <= 0.0f);
    bool pos   = (l >= 0.0f);
    bool cross = !(neg || pos);

    float all_slopes = __fdividef(vu - vl, u - l);
    float slope_u = (pos || cross) ? all_slopes : 0.0f;
    float slope_l = neg ? all_slopes : 0.0f;

    bool sw = (all_slopes < 0.0f);
    float v_l = sw ? vu : vl;
    float v_u = sw ? vl : vu;
    float b_l = sw ? u : l;
    float b_u = sw ? l : u;

    float bnd_l = cross ? -0.5f : v_l;
    float bnd_u = v_u;

    float shift_u = fmaf(-slope_u, b_u, v_u);
    float shift_l = cross ? -0.5f : fmaf(-slope_l, b_l, v_l);

    float Ud = slope_u * ls_u;
    float UV = fmaf(slope_u, lsh_u, shift_u);
    float Ld = slope_l * ls_l;
    float LV = fmaf(slope_l, lsh_l, shift_l);

    float lb = fmaf(fmaxf(Ld, 0.0f), lb_l, fmaf(fminf(Ld, 0.0f), lb_u, LV));
    float ub = fmaf(fmaxf(Ud, 0.0f), lb_u, fmaf(fminf(Ud, 0.0f), lb_l, UV));

    return make_float2(fmaxf(lb, bnd_l), fminf(ub, bnd_u));
}

__device__ __forceinline__ float4 spu_quad(float4 b, float4 ls, float4 lsh, float4 lb2) {
    float2 r0 = spu_row(b.x, b.y, ls.x, ls.y, lsh.x, lsh.y, lb2.x, lb2.y);
    float2 r1 = spu_row(b.z, b.w, ls.z, ls.w, lsh.z, lsh.w, lb2.z, lb2.w);
    return make_float4(r0.x, r0.y, r1.x, r1.y);
}

__global__ void __launch_bounds__(128, 1) spu_transformer_kernel(
    const float4* __restrict__ bounds,
    const float4* __restrict__ last_slopes,
    const float4* __restrict__ last_shifts,
    const float4* __restrict__ last_bounds,
    float4* __restrict__ out,
    int n4)
{
    int tid = blockIdx.x * blockDim.x + threadIdx.x;
    int stride = gridDim.x * blockDim.x;   // 2048: two strips cover n4=4096
    int i0 = tid;
    int i1 = tid + stride;

    if (i1 < n4) {
        // Front-batch all 8 loads: MLP=8 per thread.
        float4 b0   = bounds[i0];
        float4 b1   = bounds[i1];
        float4 ls0  = last_slopes[i0];
        float4 ls1  = last_slopes[i1];
        float4 lsh0 = last_shifts[i0];
        float4 lsh1 = last_shifts[i1];
        float4 lb0  = last_bounds[i0];
        float4 lb1  = last_bounds[i1];

        out[i0] = spu_quad(b0, ls0, lsh0, lb0);
        out[i1] = spu_quad(b1, ls1, lsh1, lb1);
    } else if (i0 < n4) {
        float4 b   = bounds[i0];
        float4 ls  = last_slopes[i0];
        float4 lsh = last_shifts[i0];
        float4 lb2 = last_bounds[i0];
        out[i0] = spu_quad(b, ls, lsh, lb2);
    }
}

extern "C" void kernel_launch(void* const* d_in, const int* in_sizes, int n_in,
                              void* d_out, int out_size) {
    const float4* bounds      = (const float4*)d_in[0];
    const float4* last_slopes = (const float4*)d_in[1];
    const float4* last_shifts = (const float4*)d_in[2];
    const float4* last_bounds = (const float4*)d_in[3];
    float4* out = (float4*)d_out;

    int n4 = in_sizes[0] / 4;                 // 4096
    const int threads = 128;
    int total_threads = (n4 + 1) / 2;         // 2 float4 per thread
    int blocks = (total_threads + threads - 1) / threads;  // 16
    spu_transformer_kernel<<<blocks, threads>>>(
        bounds, last_slopes, last_shifts, last_bounds, out, n4);
}

// round 7
// speedup vs baseline: 1.4366x; 1.4366x over previous
#include <cuda_runtime.h>

// SPU transformer bound propagation: elementwise over N=8192 rows (320 KB total
// traffic). Overhead-bound: kernel body ~500 cycles vs ~8000 cycles launch
// ramp. Best-measured config across 6 profiled variants:
//   grid 32 x block 128, float4 = 2 rows/thread, MLP=4, 32 regs,
//   fast-math sigmoid (sigmoid(-x)-1 = -e^x/(1+e^x)). rel_err ~2.5e-7.

__device__ __forceinline__ float2 spu_row(float l, float u,
                                          float ls_l, float ls_u,
                                          float lsh_l, float lsh_u,
                                          float lb_l, float lb_u) {
    // Both EX2s adjacent so the two MUFU latencies (16 cyc) overlap.
    float el = __expf(l);
    float eu = __expf(u);
    float vl_neg = __fdividef(-el, 1.0f + el);   // = sigmoid(-l) - 1
    float vu_neg = __fdividef(-eu, 1.0f + eu);
    float vl = (l >= 0.0f) ? fmaf(l, l, -0.5f) : vl_neg;
    float vu = (u >= 0.0f) ? fmaf(u, u, -0.5f) : vu_neg;

    bool neg   = (u <= 0.0f);
    bool pos   = (l >= 0.0f);
    bool cross = !(neg || pos);

    float all_slopes = __fdividef(vu - vl, u - l);
    float slope_u = (pos || cross) ? all_slopes : 0.0f;
    float slope_l = neg ? all_slopes : 0.0f;

    bool sw = (all_slopes < 0.0f);
    float v_l = sw ? vu : vl;
    float v_u = sw ? vl : vu;
    float b_l = sw ? u : l;
    float b_u = sw ? l : u;

    float bnd_l = cross ? -0.5f : v_l;
    float bnd_u = v_u;

    float shift_u = fmaf(-slope_u, b_u, v_u);
    float shift_l = cross ? -0.5f : fmaf(-slope_l, b_l, v_l);

    float Ud = slope_u * ls_u;
    float UV = fmaf(slope_u, lsh_u, shift_u);
    float Ld = slope_l * ls_l;
    float LV = fmaf(slope_l, lsh_l, shift_l);

    float lb = fmaf(fmaxf(Ld, 0.0f), lb_l, fmaf(fminf(Ld, 0.0f), lb_u, LV));
    float ub = fmaf(fmaxf(Ud, 0.0f), lb_u, fmaf(fminf(Ud, 0.0f), lb_l, UV));

    return make_float2(fmaxf(lb, bnd_l), fminf(ub, bnd_u));
}

__global__ void __launch_bounds__(128, 1) spu_transformer_kernel(
    const float4* __restrict__ bounds,
    const float4* __restrict__ last_slopes,
    const float4* __restrict__ last_shifts,
    const float4* __restrict__ last_bounds,
    float4* __restrict__ out,
    int n4)
{
    int i = blockIdx.x * blockDim.x + threadIdx.x;
    if (i < n4) {
        // 4 front-batched LDG.128 (MLP=4), then straight-line math, one STG.128.
        float4 b   = bounds[i];
        float4 ls  = last_slopes[i];
        float4 lsh = last_shifts[i];
        float4 lb2 = last_bounds[i];

        float2 r0 = spu_row(b.x, b.y, ls.x, ls.y, lsh.x, lsh.y, lb2.x, lb2.y);
        float2 r1 = spu_row(b.z, b.w, ls.z, ls.w, lsh.z, lsh.w, lb2.z, lb2.w);

        out[i] = make_float4(r0.x, r0.y, r1.x, r1.y);
    }
}

extern "C" void kernel_launch(void* const* d_in, const int* in_sizes, int n_in,
                              void* d_out, int out_size) {
    const float4* bounds      = (const float4*)d_in[0];
    const float4* last_slopes = (const float4*)d_in[1];
    const float4* last_shifts = (const float4*)d_in[2];
    const float4* last_bounds = (const float4*)d_in[3];
    float4* out = (float4*)d_out;

    int n4 = in_sizes[0] / 4;            // 8192*2 floats -> 4096 float4
    const int threads = 128;
    int blocks = (n4 + threads - 1) / threads;  // 32
    spu_transformer_kernel<<<blocks, threads>>>(
        bounds, last_slopes, last_shifts, last_bounds, out, n4);
}